// round 1
// baseline (speedup 1.0000x reference)
#include <cuda_runtime.h>
#include <math.h>

#define NN 50000
#define EE 250000
#define HD 64
#define NH 4
#define FD 256          // NH*HD
#define IND 256
#define SCALEF 0.125f   // 1/sqrt(64)
#define EPS_BN 1e-5f

// ---------------- scratch (static device globals; no allocation) -------------
__device__ float g_fs[NN * FD];
__device__ float g_fd[NN * FD];
__device__ float g_e[EE * NH];
__device__ float g_m[NN * NH];
__device__ float g_den[NN * NH];
__device__ float g_agg[NN * FD];
__device__ float g_hmean[NN * HD];
__device__ float g_h[NN * HD];
__device__ float g_bnsum[HD];
__device__ float g_bnsq[HD];

// ---------------- helpers ----------------------------------------------------
__device__ __forceinline__ void atomicMaxF(float* addr, float val) {
    int* ia = (int*)addr;
    int old = *ia;
    while (__int_as_float(old) < val) {
        int assumed = old;
        old = atomicCAS(ia, assumed, __float_as_int(val));
        if (old == assumed) break;
    }
}

__global__ void fill_kernel(float* __restrict__ p, int n, float v) {
    int i = blockIdx.x * blockDim.x + threadIdx.x;
    int stride = gridDim.x * blockDim.x;
    for (; i < n; i += stride) p[i] = v;
}

// ---------------- GEMM: C[M,Nc] = A[M,64] @ B[64,Nc] (+bias)(+relu) ----------
// Block: 256 threads -> 64x64 output tile, 4x4 microtile, K=64 resident.
template <int BIAS, int RELU>
__global__ void gemm64_kernel(const float* __restrict__ A,
                              const float* __restrict__ B,
                              const float* __restrict__ bias,
                              float* __restrict__ C, int M, int Nc) {
    __shared__ float As[64][65];
    __shared__ float Bs[64][65];
    const int bm = blockIdx.y * 64;
    const int bn = blockIdx.x * 64;
    const int tid = threadIdx.x;

    for (int i = tid; i < 64 * 64; i += 256) {
        int r = i >> 6, c = i & 63;
        int gr = bm + r;
        As[r][c] = (gr < M) ? A[gr * 64 + c] : 0.0f;
        Bs[r][c] = B[r * Nc + bn + c];
    }
    __syncthreads();

    const int tx = tid & 15, ty = tid >> 4;
    const int r0 = ty * 4, c0 = tx * 4;
    float acc[4][4] = {};
#pragma unroll
    for (int k = 0; k < 64; k++) {
        float a0 = As[r0 + 0][k], a1 = As[r0 + 1][k];
        float a2 = As[r0 + 2][k], a3 = As[r0 + 3][k];
        float b0 = Bs[k][c0 + 0], b1 = Bs[k][c0 + 1];
        float b2 = Bs[k][c0 + 2], b3 = Bs[k][c0 + 3];
        acc[0][0] += a0 * b0; acc[0][1] += a0 * b1; acc[0][2] += a0 * b2; acc[0][3] += a0 * b3;
        acc[1][0] += a1 * b0; acc[1][1] += a1 * b1; acc[1][2] += a1 * b2; acc[1][3] += a1 * b3;
        acc[2][0] += a2 * b0; acc[2][1] += a2 * b1; acc[2][2] += a2 * b2; acc[2][3] += a2 * b3;
        acc[3][0] += a3 * b0; acc[3][1] += a3 * b1; acc[3][2] += a3 * b2; acc[3][3] += a3 * b3;
    }

#pragma unroll
    for (int i = 0; i < 4; i++) {
        int gr = bm + r0 + i;
        if (gr >= M) continue;
#pragma unroll
        for (int j = 0; j < 4; j++) {
            float v = acc[i][j];
            if (BIAS) v += bias[bn + c0 + j];
            if (RELU) v = fmaxf(v, 0.0f);
            C[gr * Nc + bn + c0 + j] = v;
        }
    }
}

// ---------------- edge kernels -----------------------------------------------
// warp per edge: e[e,h] = <fs[src,h,:], fd[dst,h,:]> * scale ; atomicMax m[dst,h]
__global__ void edge_dot_kernel(const float* __restrict__ fs,
                                const float* __restrict__ fd,
                                const int* __restrict__ src,
                                const int* __restrict__ dst,
                                float* __restrict__ e, float* __restrict__ m) {
    int warp = (blockIdx.x * blockDim.x + threadIdx.x) >> 5;
    int lane = threadIdx.x & 31;
    if (warp >= EE) return;
    int s = src[warp], d = dst[warp];
    const float* ps = fs + (size_t)s * FD;
    const float* pd = fd + (size_t)d * FD;
#pragma unroll
    for (int h = 0; h < NH; h++) {
        float v = ps[h * 64 + lane] * pd[h * 64 + lane] +
                  ps[h * 64 + 32 + lane] * pd[h * 64 + 32 + lane];
#pragma unroll
        for (int off = 16; off; off >>= 1) v += __shfl_xor_sync(0xffffffffu, v, off);
        if (lane == 0) {
            v *= SCALEF;
            e[warp * NH + h] = v;
            atomicMaxF(&m[d * NH + h], v);
        }
    }
}

// thread per (edge,head): p = exp(e - m[dst]); denom[dst] += p; e <- p
__global__ void edge_exp_kernel(const int* __restrict__ dst,
                                float* __restrict__ e,
                                const float* __restrict__ m,
                                float* __restrict__ den) {
    int idx = blockIdx.x * blockDim.x + threadIdx.x;
    if (idx >= EE * NH) return;
    int edge = idx >> 2, h = idx & 3;
    int d = dst[edge];
    float p = expf(e[idx] - m[d * NH + h]);
    e[idx] = p;
    atomicAdd(&den[d * NH + h], p);
}

// warp per edge: agg[dst,h,:] += fs[src,h,:] * (p / max(den[dst,h],1e-9))
__global__ void edge_agg_kernel(const float* __restrict__ fs,
                                const int* __restrict__ src,
                                const int* __restrict__ dst,
                                const float* __restrict__ e,
                                const float* __restrict__ den,
                                float* __restrict__ agg) {
    int warp = (blockIdx.x * blockDim.x + threadIdx.x) >> 5;
    int lane = threadIdx.x & 31;
    if (warp >= EE) return;
    int s = src[warp], d = dst[warp];
    float a4 = 0.0f;
    if (lane < NH) {
        float p = e[warp * NH + lane];
        float dn = den[d * NH + lane];
        a4 = p / fmaxf(dn, 1e-9f);
    }
    float al0 = __shfl_sync(0xffffffffu, a4, 0);
    float al1 = __shfl_sync(0xffffffffu, a4, 1);
    float al2 = __shfl_sync(0xffffffffu, a4, 2);
    float al3 = __shfl_sync(0xffffffffu, a4, 3);
    const float* ps = fs + (size_t)s * FD;
    float* pa = agg + (size_t)d * FD;
    float al[4] = {al0, al1, al2, al3};
#pragma unroll
    for (int h = 0; h < NH; h++) {
        atomicAdd(&pa[h * 64 + lane], ps[h * 64 + lane] * al[h]);
        atomicAdd(&pa[h * 64 + 32 + lane], ps[h * 64 + 32 + lane] * al[h]);
    }
}

// ---------------- head mean --------------------------------------------------
__global__ void head_mean_kernel(const float* __restrict__ agg,
                                 float* __restrict__ out) {
    int idx = blockIdx.x * blockDim.x + threadIdx.x;
    if (idx >= NN * HD) return;
    int n = idx >> 6, c = idx & 63;
    const float* p = agg + (size_t)n * FD + c;
    out[idx] = 0.25f * (p[0] + p[64] + p[128] + p[192]);
}

// ---------------- batchnorm --------------------------------------------------
__global__ void bn_stats_kernel(const float* __restrict__ x,
                                float* __restrict__ bsum,
                                float* __restrict__ bsq) {
    int ch = threadIdx.x & 63;
    int rr = threadIdx.x >> 6;   // 0..3
    float s = 0.0f, s2 = 0.0f;
    for (int n = blockIdx.x * 4 + rr; n < NN; n += gridDim.x * 4) {
        float v = x[n * HD + ch];
        s += v; s2 += v * v;
    }
    __shared__ float sh[256], sh2[256];
    sh[threadIdx.x] = s; sh2[threadIdx.x] = s2;
    __syncthreads();
    if (rr == 0) {
        s  = sh[ch] + sh[64 + ch] + sh[128 + ch] + sh[192 + ch];
        s2 = sh2[ch] + sh2[64 + ch] + sh2[128 + ch] + sh2[192 + ch];
        atomicAdd(&bsum[ch], s);
        atomicAdd(&bsq[ch], s2);
    }
}

__global__ void bn_norm_kernel(float* __restrict__ x,
                               const float* __restrict__ bsum,
                               const float* __restrict__ bsq,
                               const float* __restrict__ gamma,
                               const float* __restrict__ beta) {
    int idx = blockIdx.x * blockDim.x + threadIdx.x;
    if (idx >= NN * HD) return;
    int ch = idx & 63;
    float mu = bsum[ch] * (1.0f / NN);
    float var = bsq[ch] * (1.0f / NN) - mu * mu;
    float inv = rsqrtf(var + EPS_BN);
    x[idx] = gamma[ch] * (x[idx] - mu) * inv + beta[ch];
}

// ---------------- host orchestration -----------------------------------------
extern "C" void kernel_launch(void* const* d_in, const int* in_sizes, int n_in,
                              void* d_out, int out_size) {
    const float* x    = (const float*)d_in[0];
    const int* srcs[3] = {(const int*)d_in[1], (const int*)d_in[3], (const int*)d_in[5]};
    const int* dsts[3] = {(const int*)d_in[2], (const int*)d_in[4], (const int*)d_in[6]};
    const float* Wsrc = (const float*)d_in[7];   // [2,3,64,256]
    const float* Wdst = (const float*)d_in[8];   // [2,3,64,256]
    const float* Wfc  = (const float*)d_in[9];   // [2,64,64]
    const float* bfc  = (const float*)d_in[10];  // [2,64]
    const float* gamma= (const float*)d_in[11];  // [2,64]
    const float* beta = (const float*)d_in[12];  // [2,64]
    const float* Wdim = (const float*)d_in[13];  // [64,256]
    const float* bdim = (const float*)d_in[14];  // [256]
    float* out = (float*)d_out;

    float *fs, *fd, *e, *m, *den, *agg, *hmean, *h, *bsum, *bsq;
    cudaGetSymbolAddress((void**)&fs,   g_fs);
    cudaGetSymbolAddress((void**)&fd,   g_fd);
    cudaGetSymbolAddress((void**)&e,    g_e);
    cudaGetSymbolAddress((void**)&m,    g_m);
    cudaGetSymbolAddress((void**)&den,  g_den);
    cudaGetSymbolAddress((void**)&agg,  g_agg);
    cudaGetSymbolAddress((void**)&hmean,g_hmean);
    cudaGetSymbolAddress((void**)&h,    g_h);
    cudaGetSymbolAddress((void**)&bsum, g_bnsum);
    cudaGetSymbolAddress((void**)&bsq,  g_bnsq);

    const dim3 gemm_grid_wide(4, (NN + 63) / 64);   // Nc=256
    const dim3 gemm_grid_fc(1, (NN + 63) / 64);     // Nc=64
    const int edge_warp_blocks = EE / 8;            // 8 warps/block, exact
    const int exp_blocks = (EE * NH + 255) / 256;
    const int nhd_blocks = (NN * HD + 255) / 256;

    const float* hin = x;
    for (int l = 0; l < 2; l++) {
        fill_kernel<<<2048, 256>>>(agg, NN * FD, 0.0f);
        for (int r = 0; r < 3; r++) {
            const float* Ws = Wsrc + ((size_t)(l * 3 + r)) * 64 * 256;
            const float* Wd = Wdst + ((size_t)(l * 3 + r)) * 64 * 256;
            gemm64_kernel<0, 0><<<gemm_grid_wide, 256>>>(hin, Ws, nullptr, fs, NN, FD);
            gemm64_kernel<0, 0><<<gemm_grid_wide, 256>>>(hin, Wd, nullptr, fd, NN, FD);
            fill_kernel<<<256, 256>>>(m, NN * NH, -INFINITY);
            fill_kernel<<<256, 256>>>(den, NN * NH, 0.0f);
            edge_dot_kernel<<<edge_warp_blocks, 256>>>(fs, fd, srcs[r], dsts[r], e, m);
            edge_exp_kernel<<<exp_blocks, 256>>>(dsts[r], e, m, den);
            edge_agg_kernel<<<edge_warp_blocks, 256>>>(fs, srcs[r], dsts[r], e, den, agg);
        }
        head_mean_kernel<<<nhd_blocks, 256>>>(agg, hmean);
        gemm64_kernel<1, 1><<<gemm_grid_fc, 256>>>(hmean, Wfc + (size_t)l * 64 * 64,
                                                   bfc + l * 64, h, NN, HD);
        fill_kernel<<<1, 128>>>(bsum, HD, 0.0f);
        fill_kernel<<<1, 128>>>(bsq, HD, 0.0f);
        bn_stats_kernel<<<512, 256>>>(h, bsum, bsq);
        bn_norm_kernel<<<nhd_blocks, 256>>>(h, bsum, bsq, gamma + l * 64, beta + l * 64);
        hin = h;
    }
    gemm64_kernel<1, 0><<<gemm_grid_wide, 256>>>(h, Wdim, bdim, out, NN, IND);
    (void)in_sizes; (void)n_in; (void)out_size;
}

// round 2
// speedup vs baseline: 1.4129x; 1.4129x over previous
#include <cuda_runtime.h>
#include <math.h>

#define NN 50000
#define EE 250000
#define HD 64
#define NH 4
#define FD 256          // NH*HD
#define IND 256
#define SCALEF 0.125f   // 1/sqrt(64)
#define EPS_BN 1e-5f

// ---------------- scratch (static device globals; no allocation) -------------
__device__ float g_fs[NN * FD];
__device__ float g_fd[NN * FD];
__device__ float g_p[EE * NH];
__device__ float g_den[NN * NH];
__device__ float g_hmean[NN * HD];
__device__ float g_h[NN * HD];
__device__ float g_bnsum[HD];
__device__ float g_bnsq[HD];

// ---------------- fills -------------------------------------------------------
__global__ void fill_kernel(float* __restrict__ p, int n, float v) {
    int i = blockIdx.x * blockDim.x + threadIdx.x;
    int stride = gridDim.x * blockDim.x;
    for (; i < n; i += stride) p[i] = v;
}

// ---------------- GEMM: C[M,Nc] = A[M,64] @ B[64,Nc] (+bias)(+relu) ----------
// 64x{128|64} tile, 256 threads, 4x{8|4} microtile, K=64 fully resident.
template <int BN_, int BIAS, int RELU>
__global__ void gemm_k64(const float* __restrict__ A,
                         const float* __restrict__ B,
                         const float* __restrict__ bias,
                         float* __restrict__ C, int M, int Nc) {
    constexpr int MW = BN_ / 16;          // microtile width: 8 or 4
    __shared__ float As[64][65];
    __shared__ float Bs[64][BN_ + 4];
    const int bm = blockIdx.y * 64;
    const int bn = blockIdx.x * BN_;
    const int tid = threadIdx.x;

    // load A tile (row-major, coalesced)
    for (int i = tid; i < 64 * 64; i += 256) {
        int r = i >> 6, k = i & 63;
        int gr = bm + r;
        As[r][k] = (gr < M) ? A[gr * 64 + k] : 0.0f;
    }
    // load B tile (row-major, coalesced)
    for (int i = tid; i < 64 * BN_; i += 256) {
        int k = i / BN_, c = i % BN_;
        Bs[k][c] = B[k * Nc + bn + c];
    }
    __syncthreads();

    const int tx = tid & 15, ty = tid >> 4;
    const int r0 = ty * 4, c0 = tx * MW;
    float acc[4][MW];
#pragma unroll
    for (int i = 0; i < 4; i++)
#pragma unroll
        for (int j = 0; j < MW; j++) acc[i][j] = 0.0f;

#pragma unroll 4
    for (int k = 0; k < 64; k++) {
        float a0 = As[r0 + 0][k], a1 = As[r0 + 1][k];
        float a2 = As[r0 + 2][k], a3 = As[r0 + 3][k];
        float b[MW];
#pragma unroll
        for (int j = 0; j < MW; j += 4) {
            float4 bv = *reinterpret_cast<const float4*>(&Bs[k][c0 + j]);
            b[j] = bv.x; b[j + 1] = bv.y; b[j + 2] = bv.z; b[j + 3] = bv.w;
        }
#pragma unroll
        for (int j = 0; j < MW; j++) {
            acc[0][j] += a0 * b[j];
            acc[1][j] += a1 * b[j];
            acc[2][j] += a2 * b[j];
            acc[3][j] += a3 * b[j];
        }
    }

#pragma unroll
    for (int i = 0; i < 4; i++) {
        int gr = bm + r0 + i;
        if (gr >= M) continue;
#pragma unroll
        for (int j = 0; j < MW; j += 4) {
            float4 v;
            v.x = acc[i][j];     v.y = acc[i][j + 1];
            v.z = acc[i][j + 2]; v.w = acc[i][j + 3];
            if (BIAS) {
                const float4 bb = *reinterpret_cast<const float4*>(&bias[bn + c0 + j]);
                v.x += bb.x; v.y += bb.y; v.z += bb.z; v.w += bb.w;
            }
            if (RELU) {
                v.x = fmaxf(v.x, 0.0f); v.y = fmaxf(v.y, 0.0f);
                v.z = fmaxf(v.z, 0.0f); v.w = fmaxf(v.w, 0.0f);
            }
            *reinterpret_cast<float4*>(&C[(size_t)gr * Nc + bn + c0 + j]) = v;
        }
    }
}

// ---------------- edge pass 1: dot + exp + denominator -----------------------
// warp per edge. (max-subtraction dropped: exp(e)/sum exp(e) is identical)
__global__ void edge_softmax_kernel(const float* __restrict__ fs,
                                    const float* __restrict__ fd,
                                    const int* __restrict__ src,
                                    const int* __restrict__ dst,
                                    float* __restrict__ p_out,
                                    float* __restrict__ den) {
    int warp = (blockIdx.x * blockDim.x + threadIdx.x) >> 5;
    int lane = threadIdx.x & 31;
    if (warp >= EE) return;
    int s = src[warp], d = dst[warp];
    const float* ps = fs + (size_t)s * FD;
    const float* pd = fd + (size_t)d * FD;
    float p[NH];
#pragma unroll
    for (int h = 0; h < NH; h++) {
        float v = ps[h * 64 + lane] * pd[h * 64 + lane] +
                  ps[h * 64 + 32 + lane] * pd[h * 64 + 32 + lane];
#pragma unroll
        for (int off = 16; off; off >>= 1) v += __shfl_xor_sync(0xffffffffu, v, off);
        p[h] = v;
    }
    if (lane == 0) {
        float p0 = __expf(p[0] * SCALEF) ;
        float p1 = __expf(p[1] * SCALEF);
        float p2 = __expf(p[2] * SCALEF);
        float p3 = __expf(p[3] * SCALEF);
        // NOTE: use expf precision — __expf has ~2^-21 rel err, fine vs 1e-3 tol
        float4 pv = make_float4(p0, p1, p2, p3);
        *reinterpret_cast<float4*>(p_out + 4 * (size_t)warp) = pv;
        asm volatile("red.global.add.v4.f32 [%0], {%1,%2,%3,%4};"
                     :: "l"(den + 4 * (size_t)d),
                        "f"(p0), "f"(p1), "f"(p2), "f"(p3) : "memory");
    }
}

// ---------------- edge pass 2: aggregate (head-mean folded in) ---------------
// 16 threads per edge; each thread handles 4 consecutive output channels.
// hmean[d,c] += 0.25 * sum_h alpha_h * fs[s,h,c]
__global__ void edge_agg_kernel(const float* __restrict__ fs,
                                const int* __restrict__ src,
                                const int* __restrict__ dst,
                                const float* __restrict__ p,
                                const float* __restrict__ den,
                                float* __restrict__ hmean) {
    int gid = blockIdx.x * blockDim.x + threadIdx.x;
    int e = gid >> 4;
    if (e >= EE) return;
    int q = gid & 15;
    int s = src[e], d = dst[e];
    float4 P = *reinterpret_cast<const float4*>(p + 4 * (size_t)e);
    float4 D = *reinterpret_cast<const float4*>(den + 4 * (size_t)d);
    float a0 = 0.25f * P.x / fmaxf(D.x, 1e-9f);
    float a1 = 0.25f * P.y / fmaxf(D.y, 1e-9f);
    float a2 = 0.25f * P.z / fmaxf(D.z, 1e-9f);
    float a3 = 0.25f * P.w / fmaxf(D.w, 1e-9f);
    const float4* ps = reinterpret_cast<const float4*>(fs + (size_t)s * FD);
    float4 f0 = ps[q], f1 = ps[16 + q], f2 = ps[32 + q], f3 = ps[48 + q];
    float vx = a0 * f0.x + a1 * f1.x + a2 * f2.x + a3 * f3.x;
    float vy = a0 * f0.y + a1 * f1.y + a2 * f2.y + a3 * f3.y;
    float vz = a0 * f0.z + a1 * f1.z + a2 * f2.z + a3 * f3.z;
    float vw = a0 * f0.w + a1 * f1.w + a2 * f2.w + a3 * f3.w;
    asm volatile("red.global.add.v4.f32 [%0], {%1,%2,%3,%4};"
                 :: "l"(hmean + (size_t)d * HD + q * 4),
                    "f"(vx), "f"(vy), "f"(vz), "f"(vw) : "memory");
}

// ---------------- batchnorm --------------------------------------------------
__global__ void bn_stats_kernel(const float* __restrict__ x,
                                float* __restrict__ bsum,
                                float* __restrict__ bsq) {
    int ch = threadIdx.x & 63;
    int rr = threadIdx.x >> 6;   // 0..3
    float s = 0.0f, s2 = 0.0f;
    for (int n = blockIdx.x * 4 + rr; n < NN; n += gridDim.x * 4) {
        float v = x[n * HD + ch];
        s += v; s2 += v * v;
    }
    __shared__ float sh[256], sh2[256];
    sh[threadIdx.x] = s; sh2[threadIdx.x] = s2;
    __syncthreads();
    if (rr == 0) {
        s  = sh[ch] + sh[64 + ch] + sh[128 + ch] + sh[192 + ch];
        s2 = sh2[ch] + sh2[64 + ch] + sh2[128 + ch] + sh2[192 + ch];
        atomicAdd(&bsum[ch], s);
        atomicAdd(&bsq[ch], s2);
    }
}

__global__ void bn_norm_kernel(float* __restrict__ x,
                               const float* __restrict__ bsum,
                               const float* __restrict__ bsq,
                               const float* __restrict__ gamma,
                               const float* __restrict__ beta) {
    int idx = blockIdx.x * blockDim.x + threadIdx.x;
    if (idx >= NN * HD) return;
    int ch = idx & 63;
    float mu = bsum[ch] * (1.0f / NN);
    float var = bsq[ch] * (1.0f / NN) - mu * mu;
    float inv = rsqrtf(var + EPS_BN);
    x[idx] = gamma[ch] * (x[idx] - mu) * inv + beta[ch];
}

// ---------------- host orchestration -----------------------------------------
extern "C" void kernel_launch(void* const* d_in, const int* in_sizes, int n_in,
                              void* d_out, int out_size) {
    const float* x    = (const float*)d_in[0];
    const int* srcs[3] = {(const int*)d_in[1], (const int*)d_in[3], (const int*)d_in[5]};
    const int* dsts[3] = {(const int*)d_in[2], (const int*)d_in[4], (const int*)d_in[6]};
    const float* Wsrc = (const float*)d_in[7];   // [2,3,64,256]
    const float* Wdst = (const float*)d_in[8];   // [2,3,64,256]
    const float* Wfc  = (const float*)d_in[9];   // [2,64,64]
    const float* bfc  = (const float*)d_in[10];  // [2,64]
    const float* gamma= (const float*)d_in[11];  // [2,64]
    const float* beta = (const float*)d_in[12];  // [2,64]
    const float* Wdim = (const float*)d_in[13];  // [64,256]
    const float* bdim = (const float*)d_in[14];  // [256]
    float* out = (float*)d_out;

    float *fs, *fd, *p, *den, *hmean, *h, *bsum, *bsq;
    cudaGetSymbolAddress((void**)&fs,   g_fs);
    cudaGetSymbolAddress((void**)&fd,   g_fd);
    cudaGetSymbolAddress((void**)&p,    g_p);
    cudaGetSymbolAddress((void**)&den,  g_den);
    cudaGetSymbolAddress((void**)&hmean,g_hmean);
    cudaGetSymbolAddress((void**)&h,    g_h);
    cudaGetSymbolAddress((void**)&bsum, g_bnsum);
    cudaGetSymbolAddress((void**)&bsq,  g_bnsq);

    const dim3 gemm_grid_wide(2, (NN + 63) / 64);   // BN_=128, Nc=256
    const dim3 gemm_grid_fc(1, (NN + 63) / 64);     // BN_=64,  Nc=64
    const int sm_blocks  = EE * 32 / 256;           // warp per edge, exact
    const int agg_blocks = EE * 16 / 256;           // 16 thr per edge, exact
    const int nhd_blocks = (NN * HD + 255) / 256;

    const float* hin = x;
    for (int l = 0; l < 2; l++) {
        fill_kernel<<<1024, 256>>>(hmean, NN * HD, 0.0f);
        for (int r = 0; r < 3; r++) {
            const float* Ws = Wsrc + ((size_t)(l * 3 + r)) * 64 * 256;
            const float* Wd = Wdst + ((size_t)(l * 3 + r)) * 64 * 256;
            gemm_k64<128, 0, 0><<<gemm_grid_wide, 256>>>(hin, Ws, nullptr, fs, NN, FD);
            gemm_k64<128, 0, 0><<<gemm_grid_wide, 256>>>(hin, Wd, nullptr, fd, NN, FD);
            fill_kernel<<<256, 256>>>(den, NN * NH, 0.0f);
            edge_softmax_kernel<<<sm_blocks, 256>>>(fs, fd, srcs[r], dsts[r], p, den);
            edge_agg_kernel<<<agg_blocks, 256>>>(fs, srcs[r], dsts[r], p, den, hmean);
        }
        gemm_k64<64, 1, 1><<<gemm_grid_fc, 256>>>(hmean, Wfc + (size_t)l * 64 * 64,
                                                  bfc + l * 64, h, NN, HD);
        fill_kernel<<<1, 128>>>(bsum, HD, 0.0f);
        fill_kernel<<<1, 128>>>(bsq, HD, 0.0f);
        bn_stats_kernel<<<512, 256>>>(h, bsum, bsq);
        bn_norm_kernel<<<nhd_blocks, 256>>>(h, bsum, bsq, gamma + l * 64, beta + l * 64);
        hin = h;
    }
    gemm_k64<128, 1, 0><<<gemm_grid_wide, 256>>>(h, Wdim, bdim, out, NN, IND);
    (void)in_sizes; (void)n_in; (void)out_size;
}

// round 3
// speedup vs baseline: 1.9556x; 1.3841x over previous
#include <cuda_runtime.h>
#include <math.h>

#define NN 50000
#define EE 250000
#define HD 64
#define NH 4
#define FD 256          // NH*HD
#define IND 256
#define SCALEF 0.125f   // 1/sqrt(64)
#define EPS_BN 1e-5f

// ---------------- scratch (static device globals; no allocation) -------------
__device__ float g_fs[NN * FD];
__device__ float g_fd[NN * FD];
__device__ float g_p[EE * NH];
__device__ float g_den[NN * NH];
__device__ float g_hmean[NN * HD];
__device__ float g_h[NN * HD];
__device__ float g_bnsum[HD];
__device__ float g_bnsq[HD];

// ---------------- fills -------------------------------------------------------
__global__ void fill_kernel(float* __restrict__ p, int n, float v) {
    int i = blockIdx.x * blockDim.x + threadIdx.x;
    int stride = gridDim.x * blockDim.x;
    for (; i < n; i += stride) p[i] = v;
}

// ---------------- tf32 helpers ------------------------------------------------
__device__ __forceinline__ unsigned f2tf32(float x) {
    unsigned r;
    asm("cvt.rna.tf32.f32 %0, %1;" : "=r"(r) : "f"(x));
    return r;
}
__device__ __forceinline__ void split_tf32(float x, unsigned& hi, unsigned& lo) {
    hi = f2tf32(x);
    float rem = x - __uint_as_float(hi);
    lo = f2tf32(rem);
}
__device__ __forceinline__ void mma_tf32(float& c0, float& c1, float& c2, float& c3,
                                         unsigned a0, unsigned a1, unsigned a2, unsigned a3,
                                         unsigned b0, unsigned b1) {
    asm volatile("mma.sync.aligned.m16n8k8.row.col.f32.tf32.tf32.f32 "
                 "{%0,%1,%2,%3}, {%4,%5,%6,%7}, {%8,%9}, {%0,%1,%2,%3};"
                 : "+f"(c0), "+f"(c1), "+f"(c2), "+f"(c3)
                 : "r"(a0), "r"(a1), "r"(a2), "r"(a3), "r"(b0), "r"(b1));
}

// ---------------- GEMM: C[M,Nc] = A[M,64] @ B[64,Nc] (+bias)(+relu) ----------
// 64x64 tile, 256 threads = 8 warps; warp -> 16x32 subtile (4 n-tiles of m16n8k8).
// 3xTF32 split for ~fp32 precision on tensor pipe.
template <int BIAS, int RELU>
__global__ void gemm_tf32(const float* __restrict__ A,
                          const float* __restrict__ B,
                          const float* __restrict__ bias,
                          float* __restrict__ C, int M, int Nc) {
    __shared__ float As[64][68];
    __shared__ float Bs[64][68];
    const int bm = blockIdx.y * 64;
    const int bn = blockIdx.x * 64;
    const int tid = threadIdx.x;

    // load A tile [64 rows x 64 k], coalesced float4, zero-pad OOB rows
    for (int i = tid; i < 64 * 16; i += 256) {
        int r = i >> 4, c4 = (i & 15) * 4;
        int gr = bm + r;
        float4 v = make_float4(0.f, 0.f, 0.f, 0.f);
        if (gr < M) v = *reinterpret_cast<const float4*>(&A[(size_t)gr * 64 + c4]);
        As[r][c4] = v.x; As[r][c4 + 1] = v.y; As[r][c4 + 2] = v.z; As[r][c4 + 3] = v.w;
    }
    // load B tile [64 k x 64 n], coalesced float4
    for (int i = tid; i < 64 * 16; i += 256) {
        int k = i >> 4, c4 = (i & 15) * 4;
        float4 v = *reinterpret_cast<const float4*>(&B[(size_t)k * Nc + bn + c4]);
        Bs[k][c4] = v.x; Bs[k][c4 + 1] = v.y; Bs[k][c4 + 2] = v.z; Bs[k][c4 + 3] = v.w;
    }
    __syncthreads();

    const int warp = tid >> 5, lane = tid & 31;
    const int rowg = warp >> 1, colg = warp & 1;
    const int rbase = rowg * 16, cbase = colg * 32;
    const int gid = lane >> 2, tig = lane & 3;

    float acc[4][4];
#pragma unroll
    for (int nt = 0; nt < 4; nt++)
#pragma unroll
        for (int j = 0; j < 4; j++) acc[nt][j] = 0.0f;

#pragma unroll
    for (int k0 = 0; k0 < 64; k0 += 8) {
        // A fragment (m16k8, row-major)
        float a0 = As[rbase + gid][k0 + tig];
        float a1 = As[rbase + gid + 8][k0 + tig];
        float a2 = As[rbase + gid][k0 + tig + 4];
        float a3 = As[rbase + gid + 8][k0 + tig + 4];
        unsigned ah0, al0, ah1, al1, ah2, al2, ah3, al3;
        split_tf32(a0, ah0, al0); split_tf32(a1, ah1, al1);
        split_tf32(a2, ah2, al2); split_tf32(a3, ah3, al3);
#pragma unroll
        for (int nt = 0; nt < 4; nt++) {
            int n = cbase + nt * 8 + gid;
            float b0 = Bs[k0 + tig][n];
            float b1 = Bs[k0 + tig + 4][n];
            unsigned bh0, bl0, bh1, bl1;
            split_tf32(b0, bh0, bl0); split_tf32(b1, bh1, bl1);
            mma_tf32(acc[nt][0], acc[nt][1], acc[nt][2], acc[nt][3],
                     ah0, ah1, ah2, ah3, bh0, bh1);
            mma_tf32(acc[nt][0], acc[nt][1], acc[nt][2], acc[nt][3],
                     ah0, ah1, ah2, ah3, bl0, bl1);
            mma_tf32(acc[nt][0], acc[nt][1], acc[nt][2], acc[nt][3],
                     al0, al1, al2, al3, bh0, bh1);
        }
    }

    // epilogue: c0,c1 -> row gid, cols 2*tig, 2*tig+1; c2,c3 -> row gid+8
#pragma unroll
    for (int nt = 0; nt < 4; nt++) {
        int c = bn + cbase + nt * 8 + 2 * tig;
        float bb0 = 0.f, bb1 = 0.f;
        if (BIAS) { bb0 = bias[c]; bb1 = bias[c + 1]; }
#pragma unroll
        for (int half = 0; half < 2; half++) {
            int gr = bm + rbase + gid + half * 8;
            if (gr >= M) continue;
            float v0 = acc[nt][half * 2 + 0] + bb0;
            float v1 = acc[nt][half * 2 + 1] + bb1;
            if (RELU) { v0 = fmaxf(v0, 0.0f); v1 = fmaxf(v1, 0.0f); }
            float2 v = make_float2(v0, v1);
            *reinterpret_cast<float2*>(&C[(size_t)gr * Nc + c]) = v;
        }
    }
}

// ---------------- edge pass 1: dot + exp + denominator -----------------------
// warp per edge. (max-subtraction dropped: exp(e)/sum exp(e) is identical)
__global__ void edge_softmax_kernel(const float* __restrict__ fs,
                                    const float* __restrict__ fd,
                                    const int* __restrict__ src,
                                    const int* __restrict__ dst,
                                    float* __restrict__ p_out,
                                    float* __restrict__ den) {
    int warp = (blockIdx.x * blockDim.x + threadIdx.x) >> 5;
    int lane = threadIdx.x & 31;
    if (warp >= EE) return;
    int s = src[warp], d = dst[warp];
    const float* ps = fs + (size_t)s * FD;
    const float* pd = fd + (size_t)d * FD;
    float p[NH];
#pragma unroll
    for (int h = 0; h < NH; h++) {
        float v = ps[h * 64 + lane] * pd[h * 64 + lane] +
                  ps[h * 64 + 32 + lane] * pd[h * 64 + 32 + lane];
#pragma unroll
        for (int off = 16; off; off >>= 1) v += __shfl_xor_sync(0xffffffffu, v, off);
        p[h] = v;
    }
    if (lane == 0) {
        float p0 = expf(p[0] * SCALEF);
        float p1 = expf(p[1] * SCALEF);
        float p2 = expf(p[2] * SCALEF);
        float p3 = expf(p[3] * SCALEF);
        float4 pv = make_float4(p0, p1, p2, p3);
        *reinterpret_cast<float4*>(p_out + 4 * (size_t)warp) = pv;
        asm volatile("red.global.add.v4.f32 [%0], {%1,%2,%3,%4};"
                     :: "l"(den + 4 * (size_t)d),
                        "f"(p0), "f"(p1), "f"(p2), "f"(p3) : "memory");
    }
}

// ---------------- edge pass 2: aggregate (head-mean folded in) ---------------
__global__ void edge_agg_kernel(const float* __restrict__ fs,
                                const int* __restrict__ src,
                                const int* __restrict__ dst,
                                const float* __restrict__ p,
                                const float* __restrict__ den,
                                float* __restrict__ hmean) {
    int gid = blockIdx.x * blockDim.x + threadIdx.x;
    int e = gid >> 4;
    if (e >= EE) return;
    int q = gid & 15;
    int s = src[e], d = dst[e];
    float4 P = *reinterpret_cast<const float4*>(p + 4 * (size_t)e);
    float4 D = *reinterpret_cast<const float4*>(den + 4 * (size_t)d);
    float a0 = 0.25f * P.x / fmaxf(D.x, 1e-9f);
    float a1 = 0.25f * P.y / fmaxf(D.y, 1e-9f);
    float a2 = 0.25f * P.z / fmaxf(D.z, 1e-9f);
    float a3 = 0.25f * P.w / fmaxf(D.w, 1e-9f);
    const float4* ps = reinterpret_cast<const float4*>(fs + (size_t)s * FD);
    float4 f0 = ps[q], f1 = ps[16 + q], f2 = ps[32 + q], f3 = ps[48 + q];
    float vx = a0 * f0.x + a1 * f1.x + a2 * f2.x + a3 * f3.x;
    float vy = a0 * f0.y + a1 * f1.y + a2 * f2.y + a3 * f3.y;
    float vz = a0 * f0.z + a1 * f1.z + a2 * f2.z + a3 * f3.z;
    float vw = a0 * f0.w + a1 * f1.w + a2 * f2.w + a3 * f3.w;
    asm volatile("red.global.add.v4.f32 [%0], {%1,%2,%3,%4};"
                 :: "l"(hmean + (size_t)d * HD + q * 4),
                    "f"(vx), "f"(vy), "f"(vz), "f"(vw) : "memory");
}

// ---------------- batchnorm --------------------------------------------------
__global__ void bn_stats_kernel(const float* __restrict__ x,
                                float* __restrict__ bsum,
                                float* __restrict__ bsq) {
    int ch = threadIdx.x & 63;
    int rr = threadIdx.x >> 6;   // 0..3
    float s = 0.0f, s2 = 0.0f;
    for (int n = blockIdx.x * 4 + rr; n < NN; n += gridDim.x * 4) {
        float v = x[n * HD + ch];
        s += v; s2 += v * v;
    }
    __shared__ float sh[256], sh2[256];
    sh[threadIdx.x] = s; sh2[threadIdx.x] = s2;
    __syncthreads();
    if (rr == 0) {
        s  = sh[ch] + sh[64 + ch] + sh[128 + ch] + sh[192 + ch];
        s2 = sh2[ch] + sh2[64 + ch] + sh2[128 + ch] + sh2[192 + ch];
        atomicAdd(&bsum[ch], s);
        atomicAdd(&bsq[ch], s2);
    }
}

__global__ void bn_norm_kernel(float* __restrict__ x,
                               const float* __restrict__ bsum,
                               const float* __restrict__ bsq,
                               const float* __restrict__ gamma,
                               const float* __restrict__ beta) {
    int idx = blockIdx.x * blockDim.x + threadIdx.x;
    if (idx >= NN * HD) return;
    int ch = idx & 63;
    float mu = bsum[ch] * (1.0f / NN);
    float var = bsq[ch] * (1.0f / NN) - mu * mu;
    float inv = rsqrtf(var + EPS_BN);
    x[idx] = gamma[ch] * (x[idx] - mu) * inv + beta[ch];
}

// ---------------- host orchestration -----------------------------------------
extern "C" void kernel_launch(void* const* d_in, const int* in_sizes, int n_in,
                              void* d_out, int out_size) {
    const float* x    = (const float*)d_in[0];
    const int* srcs[3] = {(const int*)d_in[1], (const int*)d_in[3], (const int*)d_in[5]};
    const int* dsts[3] = {(const int*)d_in[2], (const int*)d_in[4], (const int*)d_in[6]};
    const float* Wsrc = (const float*)d_in[7];   // [2,3,64,256]
    const float* Wdst = (const float*)d_in[8];   // [2,3,64,256]
    const float* Wfc  = (const float*)d_in[9];   // [2,64,64]
    const float* bfc  = (const float*)d_in[10];  // [2,64]
    const float* gamma= (const float*)d_in[11];  // [2,64]
    const float* beta = (const float*)d_in[12];  // [2,64]
    const float* Wdim = (const float*)d_in[13];  // [64,256]
    const float* bdim = (const float*)d_in[14];  // [256]
    float* out = (float*)d_out;

    float *fs, *fd, *p, *den, *hmean, *h, *bsum, *bsq;
    cudaGetSymbolAddress((void**)&fs,   g_fs);
    cudaGetSymbolAddress((void**)&fd,   g_fd);
    cudaGetSymbolAddress((void**)&p,    g_p);
    cudaGetSymbolAddress((void**)&den,  g_den);
    cudaGetSymbolAddress((void**)&hmean,g_hmean);
    cudaGetSymbolAddress((void**)&h,    g_h);
    cudaGetSymbolAddress((void**)&bsum, g_bnsum);
    cudaGetSymbolAddress((void**)&bsq,  g_bnsq);

    const int mtiles = (NN + 63) / 64;              // 782
    const dim3 grid_wide(4, mtiles);                // Nc=256
    const dim3 grid_fc(1, mtiles);                  // Nc=64
    const int sm_blocks  = EE * 32 / 256;           // warp per edge, exact
    const int agg_blocks = EE * 16 / 256;           // 16 thr per edge, exact
    const int nhd_blocks = (NN * HD + 255) / 256;

    const float* hin = x;
    for (int l = 0; l < 2; l++) {
        fill_kernel<<<1024, 256>>>(hmean, NN * HD, 0.0f);
        for (int r = 0; r < 3; r++) {
            const float* Ws = Wsrc + ((size_t)(l * 3 + r)) * 64 * 256;
            const float* Wd = Wdst + ((size_t)(l * 3 + r)) * 64 * 256;
            gemm_tf32<0, 0><<<grid_wide, 256>>>(hin, Ws, nullptr, fs, NN, FD);
            gemm_tf32<0, 0><<<grid_wide, 256>>>(hin, Wd, nullptr, fd, NN, FD);
            fill_kernel<<<256, 256>>>(den, NN * NH, 0.0f);
            edge_softmax_kernel<<<sm_blocks, 256>>>(fs, fd, srcs[r], dsts[r], p, den);
            edge_agg_kernel<<<agg_blocks, 256>>>(fs, srcs[r], dsts[r], p, den, hmean);
        }
        gemm_tf32<1, 1><<<grid_fc, 256>>>(hmean, Wfc + (size_t)l * 64 * 64,
                                          bfc + l * 64, h, NN, HD);
        fill_kernel<<<1, 128>>>(bsum, HD, 0.0f);
        fill_kernel<<<1, 128>>>(bsq, HD, 0.0f);
        bn_stats_kernel<<<512, 256>>>(h, bsum, bsq);
        bn_norm_kernel<<<nhd_blocks, 256>>>(h, bsum, bsq, gamma + l * 64, beta + l * 64);
        hin = h;
    }
    gemm_tf32<1, 0><<<grid_wide, 256>>>(h, Wdim, bdim, out, NN, IND);
    (void)in_sizes; (void)n_in; (void)out_size;
}

// round 4
// speedup vs baseline: 1.9644x; 1.0045x over previous
#include <cuda_runtime.h>
#include <math.h>

#define NN 50000
#define EE 250000
#define HD 64
#define NH 4
#define FDR 768         // 3 relations * 4 heads * 64
#define IND 256
#define SCALEF 0.125f   // 1/sqrt(64)
#define EPS_BN 1e-5f
#define SM_LD 68
#define GEMM_SMEM (4 * 64 * SM_LD * 4)   // Ahi,Alo,Bhi,Blo

// ---------------- scratch (static device globals; no allocation) -------------
__device__ float g_fs[(size_t)NN * FDR];
__device__ float g_fd[(size_t)NN * FDR];
__device__ float g_p[3u * EE * NH];
__device__ float g_den[3 * NN * NH];
__device__ float g_hmean[NN * HD];
__device__ float g_h[NN * HD];
__device__ float g_bnstat[2 * HD];

// ---------------- fills -------------------------------------------------------
__global__ void fill_kernel(float* __restrict__ p, int n, float v) {
    int i = blockIdx.x * blockDim.x + threadIdx.x;
    int stride = gridDim.x * blockDim.x;
    for (; i < n; i += stride) p[i] = v;
}

// ---------------- tf32 helpers ------------------------------------------------
__device__ __forceinline__ unsigned f2tf32(float x) {
    unsigned r;
    asm("cvt.rna.tf32.f32 %0, %1;" : "=r"(r) : "f"(x));
    return r;
}
__device__ __forceinline__ void split2(float x, float& hi, float& lo) {
    unsigned h = f2tf32(x);
    hi = __uint_as_float(h);
    lo = __uint_as_float(f2tf32(x - __uint_as_float(h)));
}
__device__ __forceinline__ void mma_tf32(float& c0, float& c1, float& c2, float& c3,
                                         unsigned a0, unsigned a1, unsigned a2, unsigned a3,
                                         unsigned b0, unsigned b1) {
    asm volatile("mma.sync.aligned.m16n8k8.row.col.f32.tf32.tf32.f32 "
                 "{%0,%1,%2,%3}, {%4,%5,%6,%7}, {%8,%9}, {%0,%1,%2,%3};"
                 : "+f"(c0), "+f"(c1), "+f"(c2), "+f"(c3)
                 : "r"(a0), "r"(a1), "r"(a2), "r"(a3), "r"(b0), "r"(b1));
}

// ---------------- GEMM: C[M,NcC] = A[M,64] @ B-blocks (+bias)(+relu) ---------
// 64x64 tile, 8 warps, warp -> 16x32 (4 m16n8k8 n-tiles), 3xTF32 split.
// Operands pre-split to hi/lo tf32 in dynamic smem; inner loop is LDS+MMA only.
// B addressing: column block bn selects relation (bn>>8)*64*256 + (bn&255),
// row stride ldb. Works for NcC=768 (3 rel), 256, 64.
template <int BIAS, int RELU>
__global__ void gemm_tf32s(const float* __restrict__ A,
                           const float* __restrict__ B,
                           const float* __restrict__ bias,
                           float* __restrict__ C, int M, int NcC, int ldb) {
    extern __shared__ float sm[];
    float* Ahi = sm;
    float* Alo = Ahi + 64 * SM_LD;
    float* Bhi = Alo + 64 * SM_LD;
    float* Blo = Bhi + 64 * SM_LD;

    const int bm = blockIdx.y * 64;
    const int bn = blockIdx.x * 64;
    const int tid = threadIdx.x;
    const float* Bblk = B + (size_t)(bn >> 8) * (64 * 256) + (bn & 255);

    // load + pre-split A and B tiles (vectorized, each element split once)
    for (int i = tid; i < 64 * 16; i += 256) {
        int rr = i >> 4, c4 = (i & 15) << 2;
        int gr = bm + rr;
        float4 va = make_float4(0.f, 0.f, 0.f, 0.f);
        if (gr < M) va = *reinterpret_cast<const float4*>(&A[(size_t)gr * 64 + c4]);
        float4 vh, vl;
        split2(va.x, vh.x, vl.x); split2(va.y, vh.y, vl.y);
        split2(va.z, vh.z, vl.z); split2(va.w, vh.w, vl.w);
        *reinterpret_cast<float4*>(&Ahi[rr * SM_LD + c4]) = vh;
        *reinterpret_cast<float4*>(&Alo[rr * SM_LD + c4]) = vl;

        float4 vb = *reinterpret_cast<const float4*>(&Bblk[(size_t)rr * ldb + c4]);
        split2(vb.x, vh.x, vl.x); split2(vb.y, vh.y, vl.y);
        split2(vb.z, vh.z, vl.z); split2(vb.w, vh.w, vl.w);
        *reinterpret_cast<float4*>(&Bhi[rr * SM_LD + c4]) = vh;
        *reinterpret_cast<float4*>(&Blo[rr * SM_LD + c4]) = vl;
    }
    __syncthreads();

    const int warp = tid >> 5, lane = tid & 31;
    const int rowg = warp >> 1, colg = warp & 1;
    const int rbase = rowg * 16, cbase = colg * 32;
    const int gid = lane >> 2, tig = lane & 3;

    float acc[4][4];
#pragma unroll
    for (int nt = 0; nt < 4; nt++)
#pragma unroll
        for (int j = 0; j < 4; j++) acc[nt][j] = 0.0f;

#pragma unroll
    for (int k0 = 0; k0 < 64; k0 += 8) {
        const int r0o = (rbase + gid) * SM_LD + k0 + tig;
        const int r1o = (rbase + gid + 8) * SM_LD + k0 + tig;
        unsigned ah0 = __float_as_uint(Ahi[r0o]);
        unsigned ah1 = __float_as_uint(Ahi[r1o]);
        unsigned ah2 = __float_as_uint(Ahi[r0o + 4]);
        unsigned ah3 = __float_as_uint(Ahi[r1o + 4]);
        unsigned al0 = __float_as_uint(Alo[r0o]);
        unsigned al1 = __float_as_uint(Alo[r1o]);
        unsigned al2 = __float_as_uint(Alo[r0o + 4]);
        unsigned al3 = __float_as_uint(Alo[r1o + 4]);
#pragma unroll
        for (int nt = 0; nt < 4; nt++) {
            int n = cbase + nt * 8 + gid;
            int b0o = (k0 + tig) * SM_LD + n;
            int b1o = (k0 + tig + 4) * SM_LD + n;
            unsigned bh0 = __float_as_uint(Bhi[b0o]);
            unsigned bh1 = __float_as_uint(Bhi[b1o]);
            unsigned bl0 = __float_as_uint(Blo[b0o]);
            unsigned bl1 = __float_as_uint(Blo[b1o]);
            mma_tf32(acc[nt][0], acc[nt][1], acc[nt][2], acc[nt][3],
                     ah0, ah1, ah2, ah3, bh0, bh1);
            mma_tf32(acc[nt][0], acc[nt][1], acc[nt][2], acc[nt][3],
                     ah0, ah1, ah2, ah3, bl0, bl1);
            mma_tf32(acc[nt][0], acc[nt][1], acc[nt][2], acc[nt][3],
                     al0, al1, al2, al3, bh0, bh1);
        }
    }

#pragma unroll
    for (int nt = 0; nt < 4; nt++) {
        int c = bn + cbase + nt * 8 + 2 * tig;
        float bb0 = 0.f, bb1 = 0.f;
        if (BIAS) { bb0 = bias[c]; bb1 = bias[c + 1]; }
#pragma unroll
        for (int half = 0; half < 2; half++) {
            int gr = bm + rbase + gid + half * 8;
            if (gr >= M) continue;
            float v0 = acc[nt][half * 2 + 0] + bb0;
            float v1 = acc[nt][half * 2 + 1] + bb1;
            if (RELU) { v0 = fmaxf(v0, 0.0f); v1 = fmaxf(v1, 0.0f); }
            *reinterpret_cast<float2*>(&C[(size_t)gr * NcC + c]) = make_float2(v0, v1);
        }
    }
}

// ---------------- edge pass 1: dot + exp + denominator (all 3 relations) -----
// warp per (relation, edge); 8 lanes per head, 2x float4 loads per lane.
__global__ void edge_softmax_all(const float* __restrict__ fs,
                                 const float* __restrict__ fd,
                                 const int* __restrict__ src0, const int* __restrict__ dst0,
                                 const int* __restrict__ src1, const int* __restrict__ dst1,
                                 const int* __restrict__ src2, const int* __restrict__ dst2,
                                 float* __restrict__ p_out, float* __restrict__ den) {
    int gw = blockIdx.x * 8 + (threadIdx.x >> 5);
    if (gw >= 3 * EE) return;
    int r = gw / EE, e = gw - r * EE;
    const int* sp = (r == 0) ? src0 : (r == 1) ? src1 : src2;
    const int* dp = (r == 0) ? dst0 : (r == 1) ? dst1 : dst2;
    int s = sp[e], d = dp[e];
    int lane = threadIdx.x & 31;
    int h = lane >> 3, sub = lane & 7;
    const float4* ps = reinterpret_cast<const float4*>(fs + (size_t)s * FDR + r * 256 + h * 64) + sub * 2;
    const float4* pd = reinterpret_cast<const float4*>(fd + (size_t)d * FDR + r * 256 + h * 64) + sub * 2;
    float4 a0 = ps[0], a1 = ps[1];
    float4 b0 = pd[0], b1 = pd[1];
    float v = a0.x * b0.x + a0.y * b0.y + a0.z * b0.z + a0.w * b0.w +
              a1.x * b1.x + a1.y * b1.y + a1.z * b1.z + a1.w * b1.w;
    v += __shfl_xor_sync(0xffffffffu, v, 4);
    v += __shfl_xor_sync(0xffffffffu, v, 2);
    v += __shfl_xor_sync(0xffffffffu, v, 1);
    if (sub == 0) {
        float pv = expf(v * SCALEF);
        p_out[(size_t)gw * 4 + h] = pv;
        atomicAdd(&den[((size_t)r * NN + d) * 4 + h], pv);
    }
}

// ---------------- edge pass 2: aggregate, head-mean folded, all relations ----
__global__ void edge_agg_all(const float* __restrict__ fs,
                             const int* __restrict__ src0,
                             const int* __restrict__ src1,
                             const int* __restrict__ src2,
                             const int* __restrict__ dst0,
                             const int* __restrict__ dst1,
                             const int* __restrict__ dst2,
                             const float* __restrict__ p,
                             const float* __restrict__ den,
                             float* __restrict__ hmean) {
    int gid = blockIdx.x * blockDim.x + threadIdx.x;
    int ge = gid >> 4;
    if (ge >= 3 * EE) return;
    int q = gid & 15;
    int r = ge / EE, e = ge - r * EE;
    const int* sp = (r == 0) ? src0 : (r == 1) ? src1 : src2;
    const int* dp = (r == 0) ? dst0 : (r == 1) ? dst1 : dst2;
    int s = sp[e], d = dp[e];
    float4 P = *reinterpret_cast<const float4*>(p + (size_t)ge * 4);
    float4 D = *reinterpret_cast<const float4*>(den + ((size_t)r * NN + d) * 4);
    float a0 = 0.25f * P.x / fmaxf(D.x, 1e-9f);
    float a1 = 0.25f * P.y / fmaxf(D.y, 1e-9f);
    float a2 = 0.25f * P.z / fmaxf(D.z, 1e-9f);
    float a3 = 0.25f * P.w / fmaxf(D.w, 1e-9f);
    const float4* ps = reinterpret_cast<const float4*>(fs + (size_t)s * FDR + r * 256);
    float4 f0 = ps[q], f1 = ps[16 + q], f2 = ps[32 + q], f3 = ps[48 + q];
    float vx = a0 * f0.x + a1 * f1.x + a2 * f2.x + a3 * f3.x;
    float vy = a0 * f0.y + a1 * f1.y + a2 * f2.y + a3 * f3.y;
    float vz = a0 * f0.z + a1 * f1.z + a2 * f2.z + a3 * f3.z;
    float vw = a0 * f0.w + a1 * f1.w + a2 * f2.w + a3 * f3.w;
    asm volatile("red.global.add.v4.f32 [%0], {%1,%2,%3,%4};"
                 :: "l"(hmean + (size_t)d * HD + q * 4),
                    "f"(vx), "f"(vy), "f"(vz), "f"(vw) : "memory");
}

// ---------------- batchnorm --------------------------------------------------
__global__ void bn_stats_kernel(const float* __restrict__ x,
                                float* __restrict__ bnstat) {
    int ch = threadIdx.x & 63;
    int rr = threadIdx.x >> 6;   // 0..3
    float s = 0.0f, s2 = 0.0f;
    for (int n = blockIdx.x * 4 + rr; n < NN; n += gridDim.x * 4) {
        float v = x[n * HD + ch];
        s += v; s2 += v * v;
    }
    __shared__ float sh[256], sh2[256];
    sh[threadIdx.x] = s; sh2[threadIdx.x] = s2;
    __syncthreads();
    if (rr == 0) {
        s  = sh[ch] + sh[64 + ch] + sh[128 + ch] + sh[192 + ch];
        s2 = sh2[ch] + sh2[64 + ch] + sh2[128 + ch] + sh2[192 + ch];
        atomicAdd(&bnstat[ch], s);
        atomicAdd(&bnstat[64 + ch], s2);
    }
}

__global__ void bn_norm_kernel(float* __restrict__ x,
                               const float* __restrict__ bnstat,
                               const float* __restrict__ gamma,
                               const float* __restrict__ beta) {
    int idx = blockIdx.x * blockDim.x + threadIdx.x;
    if (idx >= NN * HD) return;
    int ch = idx & 63;
    float mu = bnstat[ch] * (1.0f / NN);
    float var = bnstat[64 + ch] * (1.0f / NN) - mu * mu;
    float inv = rsqrtf(var + EPS_BN);
    x[idx] = gamma[ch] * (x[idx] - mu) * inv + beta[ch];
}

// ---------------- host orchestration -----------------------------------------
extern "C" void kernel_launch(void* const* d_in, const int* in_sizes, int n_in,
                              void* d_out, int out_size) {
    const float* x    = (const float*)d_in[0];
    const int* src0 = (const int*)d_in[1];
    const int* dst0 = (const int*)d_in[2];
    const int* src1 = (const int*)d_in[3];
    const int* dst1 = (const int*)d_in[4];
    const int* src2 = (const int*)d_in[5];
    const int* dst2 = (const int*)d_in[6];
    const float* Wsrc = (const float*)d_in[7];   // [2,3,64,256]
    const float* Wdst = (const float*)d_in[8];   // [2,3,64,256]
    const float* Wfc  = (const float*)d_in[9];   // [2,64,64]
    const float* bfc  = (const float*)d_in[10];  // [2,64]
    const float* gamma= (const float*)d_in[11];  // [2,64]
    const float* beta = (const float*)d_in[12];  // [2,64]
    const float* Wdim = (const float*)d_in[13];  // [64,256]
    const float* bdim = (const float*)d_in[14];  // [256]
    float* out = (float*)d_out;

    float *fs, *fd, *p, *den, *hmean, *h, *bnstat;
    cudaGetSymbolAddress((void**)&fs,    g_fs);
    cudaGetSymbolAddress((void**)&fd,    g_fd);
    cudaGetSymbolAddress((void**)&p,     g_p);
    cudaGetSymbolAddress((void**)&den,   g_den);
    cudaGetSymbolAddress((void**)&hmean, g_hmean);
    cudaGetSymbolAddress((void**)&h,     g_h);
    cudaGetSymbolAddress((void**)&bnstat,g_bnstat);

    cudaFuncSetAttribute(gemm_tf32s<0, 0>, cudaFuncAttributeMaxDynamicSharedMemorySize, GEMM_SMEM);
    cudaFuncSetAttribute(gemm_tf32s<1, 1>, cudaFuncAttributeMaxDynamicSharedMemorySize, GEMM_SMEM);
    cudaFuncSetAttribute(gemm_tf32s<1, 0>, cudaFuncAttributeMaxDynamicSharedMemorySize, GEMM_SMEM);

    const int mtiles = (NN + 63) / 64;              // 782
    const dim3 grid_proj(12, mtiles);               // NcC=768
    const dim3 grid_fc(1, mtiles);                  // NcC=64
    const dim3 grid_out(4, mtiles);                 // NcC=256
    const int sm_blocks  = 3 * EE / 8;              // warp per (rel,edge)
    const int agg_blocks = 3 * EE * 16 / 256;
    const int nhd_blocks = (NN * HD + 255) / 256;

    const float* hin = x;
    for (int l = 0; l < 2; l++) {
        const float* Ws = Wsrc + (size_t)l * 3 * 64 * 256;
        const float* Wd = Wdst + (size_t)l * 3 * 64 * 256;
        fill_kernel<<<1024, 256>>>(hmean, NN * HD, 0.0f);
        fill_kernel<<<512, 256>>>(den, 3 * NN * NH, 0.0f);
        gemm_tf32s<0, 0><<<grid_proj, 256, GEMM_SMEM>>>(hin, Ws, nullptr, fs, NN, FDR, 256);
        gemm_tf32s<0, 0><<<grid_proj, 256, GEMM_SMEM>>>(hin, Wd, nullptr, fd, NN, FDR, 256);
        edge_softmax_all<<<sm_blocks, 256>>>(fs, fd, src0, dst0, src1, dst1, src2, dst2, p, den);
        edge_agg_all<<<agg_blocks, 256>>>(fs, src0, src1, src2, dst0, dst1, dst2, p, den, hmean);
        gemm_tf32s<1, 1><<<grid_fc, 256, GEMM_SMEM>>>(hmean, Wfc + (size_t)l * 64 * 64,
                                                      bfc + l * 64, h, NN, HD, 64);
        fill_kernel<<<1, 128>>>(bnstat, 2 * HD, 0.0f);
        bn_stats_kernel<<<512, 256>>>(h, bnstat);
        bn_norm_kernel<<<nhd_blocks, 256>>>(h, bnstat, gamma + l * 64, beta + l * 64);
        hin = h;
    }
    gemm_tf32s<1, 0><<<grid_out, 256, GEMM_SMEM>>>(h, Wdim, bdim, out, NN, IND, 256);
    (void)in_sizes; (void)n_in; (void)out_size;
}